// round 7
// baseline (speedup 1.0000x reference)
#include <cuda_runtime.h>
#include <cuda_bf16.h>
#include <cstdint>

#define Hn   128
#define Bn   64
#define Tn   128
#define Ln   2
#define LATn 512
#define UNF  6
#define EPSV 1e-8f
#define TOTAL (Tn * UNF)

// ---------------- static device scratch ----------------
__device__ float g_par[Ln][6][Hn * Hn];
__device__ float g_cn[Ln][Hn];         // column sums of rec_hwe
__device__ float g_cd[Ln][Hn];         // column sums of |rec_hwe|
__device__ float g_ns[Tn * Bn * Hn];   // sensory numerator  [T,B,H]
__device__ float g_ds[Tn * Bn * Hn];   // sensory denominator [T,B,H]
__device__ float g_h0[Tn * Bn * Hn];   // layer-0 hidden seq [T,B,H]
__device__ float g_h1[Bn * Tn * Hn];   // layer-1 hidden, flat [B, T*H]

__device__ __forceinline__ float tanh_fast(float x) {
    float y;
    asm("tanh.approx.f32 %0, %1;" : "=f"(y) : "f"(x));
    return y;
}

// ---------------- param transform ----------------
__global__ void prep_kernel(const float* __restrict__ sg,  const float* __restrict__ mu,
                            const float* __restrict__ w,   const float* __restrict__ er,
                            const float* __restrict__ ssg, const float* __restrict__ smu,
                            const float* __restrict__ sw,  const float* __restrict__ ser)
{
    int idx = blockIdx.x * blockDim.x + threadIdx.x;
    if (idx >= Ln * Hn * Hn) return;
    int l = idx >> 14;
    int k = idx & (Hn * Hn - 1);
    float a = sg[idx], m = mu[idx];
    g_par[l][0][k] = 0.5f * a;
    g_par[l][1][k] = -0.5f * m * a;
    g_par[l][2][k] = 0.5f * w[idx] * er[idx];
    float sa = ssg[idx], sm2 = smu[idx];
    g_par[l][3][k] = 0.5f * sa;
    g_par[l][4][k] = -0.5f * sm2 * sa;
    g_par[l][5][k] = 0.5f * sw[idx] * ser[idx];
}

__global__ void csum_kernel()
{
    int l = blockIdx.x;
    int j = threadIdx.x;
    float n = 0.f, d = 0.f;
    for (int i = 0; i < Hn; i++) {
        float h = g_par[l][2][i * Hn + j];
        n += h;
        d += fabsf(h);
    }
    g_cn[l][j] = n;
    g_cd[l][j] = d;
}

// ---------------- sensory precompute ----------------
__global__ void __launch_bounds__(256) sensory_kernel(int layer, const float* __restrict__ x)
{
    __shared__ float su[4][Hn];
    __shared__ float pn[4][8][Hn];
    __shared__ float pd[4][8][Hn];

    const int tg   = blockIdx.x;
    const int b    = blockIdx.y;
    const int t0   = tg * 4;
    const int tid  = threadIdx.x;
    const int w    = tid >> 5;
    const int lane = tid & 31;

    const float* ub; int ust, usb;
    if (layer == 0) { ub = x;    ust = Hn;      usb = Tn * Hn; }
    else            { ub = g_h0; ust = Bn * Hn; usb = Hn;      }

    for (int k = tid; k < 4 * Hn; k += 256) {
        int tt = k >> 7, i = k & 127;
        su[tt][i] = ub[(size_t)b * usb + (size_t)(t0 + tt) * ust + i];
    }
    __syncthreads();

    const float4* pa = (const float4*)g_par[layer][3];
    const float4* pb = (const float4*)g_par[layer][4];
    const float4* pw = (const float4*)g_par[layer][5];

    float4 an[4], ad[4];
#pragma unroll
    for (int tt = 0; tt < 4; tt++) { an[tt] = make_float4(0,0,0,0); ad[tt] = make_float4(0,0,0,0); }

#pragma unroll 2
    for (int ii = 0; ii < 16; ii++) {
        int i = w * 16 + ii;
        float4 A  = pa[i * 32 + lane];
        float4 Bv = pb[i * 32 + lane];
        float4 W  = pw[i * 32 + lane];
#pragma unroll
        for (int tt = 0; tt < 4; tt++) {
            float vi = su[tt][i];
            float th, tv;
            th = tanh_fast(fmaf(vi, A.x, Bv.x)); tv = fmaf(W.x, th, W.x); an[tt].x += tv; ad[tt].x += fabsf(tv);
            th = tanh_fast(fmaf(vi, A.y, Bv.y)); tv = fmaf(W.y, th, W.y); an[tt].y += tv; ad[tt].y += fabsf(tv);
            th = tanh_fast(fmaf(vi, A.z, Bv.z)); tv = fmaf(W.z, th, W.z); an[tt].z += tv; ad[tt].z += fabsf(tv);
            th = tanh_fast(fmaf(vi, A.w, Bv.w)); tv = fmaf(W.w, th, W.w); an[tt].w += tv; ad[tt].w += fabsf(tv);
        }
    }
#pragma unroll
    for (int tt = 0; tt < 4; tt++) {
        ((float4*)&pn[tt][w][0])[lane] = an[tt];
        ((float4*)&pd[tt][w][0])[lane] = ad[tt];
    }
    __syncthreads();

    for (int p = tid; p < 512; p += 256) {
        int tt = p >> 7, j = p & 127;
        float n = 0.f, d = 0.f;
#pragma unroll
        for (int c = 0; c < 8; c++) { n += pn[tt][c][j]; d += pd[tt][c][j]; }
        int off = ((t0 + tt) * Bn + b) * Hn + j;
        g_ns[off] = n;
        g_ds[off] = d;
    }
}

// ---------------- LTC scan: cluster-of-4, TWO interleaved chains per CTA ----------------
// 128 CTAs of 256 threads; cluster (4,1,1) spans TWO batches (chains A=2c, B=2c+1).
// Rank r owns j in [32r, 32r+32) for both chains. Per round: waitA -> computeA ->
// sendA -> waitB -> computeB -> sendB -> one __syncthreads. Chain A's DSMEM
// round-trip hides under chain B's compute and vice versa. Weight registers are
// shared between chains; per-chain state: vj, ns/ds, s_v[2][128], 2 mbar slots.
__global__ void __launch_bounds__(256, 1) __cluster_dims__(4, 1, 1)
scan_kernel(int layer, const float* __restrict__ gleak, const float* __restrict__ vleak,
            const float* __restrict__ cm)
{
    __shared__ float s_v[2][2][Hn];                       // [chain][buf][j]
    __shared__ __align__(16) unsigned long long s_mbar[4]; // chain*2 + slot

    const int tid  = threadIdx.x;
    const int w    = tid >> 5;        // 0..7
    const int lane = tid & 31;
    const int s    = lane & 7;        // i-slice within j-group
    const int jj   = lane >> 3;       // which of the warp's 4 j's
    const int b0   = (blockIdx.x >> 2) * 2;   // chain A batch; B = b0+1

    unsigned int rank;
    asm("mov.u32 %0, %%cluster_ctarank;" : "=r"(rank));

    const int jg      = (int)rank * 32 + w * 4 + jj;
    const bool leader = (s == 0);

    const unsigned int mbar_addr = (unsigned int)__cvta_generic_to_shared(&s_mbar[0]);
    if (tid == 0) {
#pragma unroll
        for (int m = 0; m < 4; m++)
            asm volatile("mbarrier.init.shared.b64 [%0], 1;" :: "r"(mbar_addr + 8u * m) : "memory");
    }
    if (tid < Hn) {
        s_v[0][0][tid] = 0.f; s_v[0][1][tid] = 0.f;
        s_v[1][0][tid] = 0.f; s_v[1][1][tid] = 0.f;
    }

    // ---- shared params into registers: k = 4q+m  ->  i = 32q + 4s + m
    float A[16], B[16], W[16];
    {
        const float* pa = g_par[layer][0];
        const float* pb = g_par[layer][1];
        const float* pw = g_par[layer][2];
#pragma unroll
        for (int q = 0; q < 4; q++)
#pragma unroll
            for (int m = 0; m < 4; m++) {
                int off = (32 * q + 4 * s + m) * Hn + jg;
                A[4*q+m] = pa[off]; B[4*q+m] = pb[off]; W[4*q+m] = pw[off];
            }
    }

    // per-j constants (leader only uses them)
    float g   = gleak[layer * Hn + jg];
    float vv  = vleak[layer * Hn + jg];
    float c   = cm[layer * Hn + jg];
    const float cmt  = c * (float)UNF;
    const float glr  = g;
    const float glvl = g * vv;
    const float cbn  = g_cn[layer][jg];
    const float cbd  = g_cd[layer][jg];

    // remote base addresses for the 3 peers (chain offsets are additive:
    // peer SMEM layout is congruent, so peer_addr(x+delta) = peer_addr(x)+delta)
    unsigned int sv_rem[3], mb_rem[3];
    {
        unsigned int la = (unsigned int)__cvta_generic_to_shared(&s_v[0][0][jg]);
        int p = 0;
#pragma unroll
        for (unsigned int r = 0; r < 4; r++) {
            if (r == rank) continue;
            asm("mapa.shared::cluster.u32 %0, %1, %2;" : "=r"(sv_rem[p]) : "r"(la), "r"(r));
            asm("mapa.shared::cluster.u32 %0, %1, %2;" : "=r"(mb_rem[p]) : "r"(mbar_addr), "r"(r));
            p++;
        }
    }

    __syncthreads();
    asm volatile("barrier.cluster.arrive.aligned;" ::: "memory");
    asm volatile("barrier.cluster.wait.aligned;"   ::: "memory");

    float* hout; int st_t, st_b;
    if (layer == 0) { hout = g_h0; st_t = Bn * Hn; st_b = Hn;      }
    else            { hout = g_h1; st_t = Hn;      st_b = Tn * Hn; }

#define STEP(vi, k) { float th = tanh_fast(fmaf((vi), A[k], B[k])); \
                      accn = fmaf(W[k], th, accn); accd = fmaf(fabsf(W[k]), th, accd); }

// wait on chain ch's mbar for data sent at round (cnt-1)
#define CHAIN_WAIT(ch) { \
    const unsigned int wslot = (unsigned)(ch) * 2u + (unsigned)((cnt - 1) & 1); \
    const unsigned int wpar  = (unsigned)(((cnt - 1) >> 1) & 1); \
    asm volatile( \
        "{\n\t" \
        ".reg .pred P;\n\t" \
        "WAIT_%=: \n\t" \
        "mbarrier.try_wait.parity.acquire.cta.shared::cta.b64 P, [%0], %1, 0x989680;\n\t" \
        "@P bra.uni DONE_%=;\n\t" \
        "bra.uni WAIT_%=;\n\t" \
        "DONE_%=:\n\t" \
        "}" :: "r"(mbar_addr + 8u * wslot), "r"(wpar) : "memory"); }

// compute + reduce + leader update/send for chain ch
#define CHAIN_BODY(ch, vjv, nsrv, dsrv) { \
    float accn = 0.f, accd = 0.f; \
    _Pragma("unroll") \
    for (int q = 0; q < 4; q++) { \
        float4 vq = *(const float4*)&s_v[ch][curb][32 * q + 4 * s]; \
        STEP(vq.x, 4*q+0) STEP(vq.y, 4*q+1) STEP(vq.z, 4*q+2) STEP(vq.w, 4*q+3) \
    } \
    accn += __shfl_xor_sync(0xffffffffu, accn, 1, 8); \
    accd += __shfl_xor_sync(0xffffffffu, accd, 1, 8); \
    accn += __shfl_xor_sync(0xffffffffu, accn, 2, 8); \
    accd += __shfl_xor_sync(0xffffffffu, accd, 2, 8); \
    accn += __shfl_xor_sync(0xffffffffu, accn, 4, 8); \
    accd += __shfl_xor_sync(0xffffffffu, accd, 4, 8); \
    if (leader) { \
        float n = (nsrv) + accn, d = (dsrv) + accd; \
        float vnew = __fdividef(fmaf(cmt, (vjv), glvl) + n, cmt + glr + d + EPSV); \
        (vjv) = vnew; \
        s_v[ch][nxtb][jg] = vnew; \
        if (cnt < TOTAL - 1) { \
            unsigned int vbits = __float_as_uint(vnew); \
            unsigned int doff = (unsigned)(ch) * 1024u + 512u * (unsigned)nxtb; \
            unsigned int moff = (unsigned)(ch) * 16u + 8u * (unsigned)curb; \
            _Pragma("unroll") \
            for (int p = 0; p < 3; p++) { \
                asm volatile("st.async.shared::cluster.mbarrier::complete_tx::bytes.b32 [%0], %1, [%2];" \
                             :: "r"(sv_rem[p] + doff), "r"(vbits), \
                                "r"(mb_rem[p] + moff) : "memory"); \
            } \
        } \
    } }

    float vjA = 0.f, vjB = 0.f;
    int cnt = 0;
    for (int t = 0; t < Tn; t++) {
        float nsrA = 0.f, dsrA = 0.f, nsrB = 0.f, dsrB = 0.f;
        if (leader) {
            int offA = (t * Bn + b0) * Hn + jg;
            nsrA = g_ns[offA] + cbn;       dsrA = g_ds[offA] + cbd;
            nsrB = g_ns[offA + Hn] + cbn;  dsrB = g_ds[offA + Hn] + cbd;
        }
#pragma unroll 1
        for (int u = 0; u < UNF; u++) {
            const int curb = cnt & 1;
            const int nxtb = curb ^ 1;
            if (tid == 0 && cnt < TOTAL - 1) {
                asm volatile("mbarrier.arrive.expect_tx.shared.b64 _, [%0], 384;"
                             :: "r"(mbar_addr + 8u * (unsigned)curb) : "memory");
                asm volatile("mbarrier.arrive.expect_tx.shared.b64 _, [%0], 384;"
                             :: "r"(mbar_addr + 16u + 8u * (unsigned)curb) : "memory");
            }
            if (cnt > 0) CHAIN_WAIT(0)
            CHAIN_BODY(0, vjA, nsrA, dsrA)
            if (cnt > 0) CHAIN_WAIT(1)
            CHAIN_BODY(1, vjB, nsrB, dsrB)
            __syncthreads();
            cnt++;
        }
        if (leader) {
            hout[(size_t)t * st_t + (size_t)b0 * st_b + jg]       = vjA;
            hout[(size_t)t * st_t + (size_t)(b0 + 1) * st_b + jg] = vjB;
        }
    }
#undef STEP
#undef CHAIN_WAIT
#undef CHAIN_BODY
    asm volatile("barrier.cluster.arrive.aligned;" ::: "memory");
    asm volatile("barrier.cluster.wait.aligned;"   ::: "memory");
}

// ---------------- dual linear heads ----------------
__global__ void __launch_bounds__(256) head_kernel(
    const float* __restrict__ mu_w, const float* __restrict__ mu_b,
    const float* __restrict__ ls_w, const float* __restrict__ ls_b,
    float* __restrict__ out)
{
    __shared__ float  sh[64][129];
    __shared__ float4 swt[8][32];
    const int tid = threadIdx.x;
    const int bb  = tid & 63;
    const int ng  = tid >> 6;
    const int n0  = blockIdx.x * 8;
    const bool is_ls = (n0 >= LATn);
    const float* wbase = is_ls ? (ls_w + (size_t)(n0 - LATn) * (Tn * Hn))
                               : (mu_w + (size_t)n0 * (Tn * Hn));
    float acc0 = 0.f, acc1 = 0.f;

    for (int k0 = 0; k0 < Tn * Hn; k0 += 128) {
        __syncthreads();
        for (int q = tid; q < 2048; q += 256) {
            int r = q >> 5, kq = q & 31;
            float4 v = *(const float4*)(g_h1 + (size_t)r * (Tn * Hn) + k0 + kq * 4);
            sh[r][kq*4+0] = v.x; sh[r][kq*4+1] = v.y; sh[r][kq*4+2] = v.z; sh[r][kq*4+3] = v.w;
        }
        {
            int r = tid >> 5, kq = tid & 31;
            swt[r][kq] = *(const float4*)(wbase + (size_t)r * (Tn * Hn) + k0 + kq * 4);
        }
        __syncthreads();
        const int na = ng * 2, nb = ng * 2 + 1;
#pragma unroll 8
        for (int kq = 0; kq < 32; kq++) {
            float4 w0 = swt[na][kq];
            float4 w1 = swt[nb][kq];
            float h0v = sh[bb][kq*4+0], h1v = sh[bb][kq*4+1];
            float h2v = sh[bb][kq*4+2], h3v = sh[bb][kq*4+3];
            acc0 = fmaf(h0v, w0.x, fmaf(h1v, w0.y, fmaf(h2v, w0.z, fmaf(h3v, w0.w, acc0))));
            acc1 = fmaf(h0v, w1.x, fmaf(h1v, w1.y, fmaf(h2v, w1.z, fmaf(h3v, w1.w, acc1))));
        }
    }
    int na_g = n0 + ng * 2;
    float o0, o1;
    if (!is_ls) { o0 = acc0 + mu_b[na_g];              o1 = acc1 + mu_b[na_g + 1]; }
    else        { o0 = expf(acc0 + ls_b[na_g - LATn]); o1 = expf(acc1 + ls_b[na_g - LATn + 1]); }
    int outcol = is_ls ? (na_g - LATn) : na_g;
    float* ob = out + (is_ls ? (size_t)Bn * LATn : 0);
    ob[(size_t)bb * LATn + outcol]     = o0;
    ob[(size_t)bb * LATn + outcol + 1] = o1;
}

// ---------------- launch ----------------
extern "C" void kernel_launch(void* const* d_in, const int* in_sizes, int n_in,
                              void* d_out, int out_size)
{
    const float* x      = (const float*)d_in[0];
    const float* gleak  = (const float*)d_in[1];
    const float* vleak  = (const float*)d_in[2];
    const float* cm     = (const float*)d_in[3];
    const float* sigma  = (const float*)d_in[4];
    const float* mu_syn = (const float*)d_in[5];
    const float* w      = (const float*)d_in[6];
    const float* erev   = (const float*)d_in[7];
    const float* s_sig  = (const float*)d_in[8];
    const float* s_mu   = (const float*)d_in[9];
    const float* s_w    = (const float*)d_in[10];
    const float* s_er   = (const float*)d_in[11];
    const float* mu_w   = (const float*)d_in[12];
    const float* mu_b   = (const float*)d_in[13];
    const float* ls_w   = (const float*)d_in[14];
    const float* ls_b   = (const float*)d_in[15];
    float* out = (float*)d_out;

    prep_kernel<<<(Ln * Hn * Hn + 511) / 512, 512>>>(sigma, mu_syn, w, erev, s_sig, s_mu, s_w, s_er);
    csum_kernel<<<Ln, Hn>>>();

    dim3 sgrid(Tn / 4, Bn);
    sensory_kernel<<<sgrid, 256>>>(0, x);
    scan_kernel<<<2 * Bn, 256>>>(0, gleak, vleak, cm);   // 128 CTAs = 32 clusters x 2 batches
    sensory_kernel<<<sgrid, 256>>>(1, x);
    scan_kernel<<<2 * Bn, 256>>>(1, gleak, vleak, cm);
    head_kernel<<<(2 * LATn) / 8, 256>>>(mu_w, mu_b, ls_w, ls_b, out);
}

// round 8
// speedup vs baseline: 1.3901x; 1.3901x over previous
#include <cuda_runtime.h>
#include <cuda_bf16.h>
#include <cstdint>

#define Hn   128
#define Bn   64
#define Tn   128
#define Ln   2
#define LATn 512
#define UNF  6
#define EPSV 1e-8f
#define TOTAL (Tn * UNF)

// ---------------- static device scratch ----------------
__device__ float g_par[Ln][6][Hn * Hn];
__device__ float g_cn[Ln][Hn];         // column sums of rec_hwe
__device__ float g_cd[Ln][Hn];         // column sums of |rec_hwe|
__device__ float g_ns[Tn * Bn * Hn];   // sensory numerator  [T,B,H]
__device__ float g_ds[Tn * Bn * Hn];   // sensory denominator [T,B,H]
__device__ float g_h0[Tn * Bn * Hn];   // layer-0 hidden seq [T,B,H]
__device__ float g_h1[Bn * Tn * Hn];   // layer-1 hidden, flat [B, T*H]

__device__ __forceinline__ float tanh_fast(float x) {
    float y;
    asm("tanh.approx.f32 %0, %1;" : "=f"(y) : "f"(x));
    return y;
}

// ---------------- param transform ----------------
__global__ void prep_kernel(const float* __restrict__ sg,  const float* __restrict__ mu,
                            const float* __restrict__ w,   const float* __restrict__ er,
                            const float* __restrict__ ssg, const float* __restrict__ smu,
                            const float* __restrict__ sw,  const float* __restrict__ ser)
{
    int idx = blockIdx.x * blockDim.x + threadIdx.x;
    if (idx >= Ln * Hn * Hn) return;
    int l = idx >> 14;
    int k = idx & (Hn * Hn - 1);
    float a = sg[idx], m = mu[idx];
    g_par[l][0][k] = 0.5f * a;
    g_par[l][1][k] = -0.5f * m * a;
    g_par[l][2][k] = 0.5f * w[idx] * er[idx];
    float sa = ssg[idx], sm2 = smu[idx];
    g_par[l][3][k] = 0.5f * sa;
    g_par[l][4][k] = -0.5f * sm2 * sa;
    g_par[l][5][k] = 0.5f * sw[idx] * ser[idx];
}

__global__ void csum_kernel()
{
    int l = blockIdx.x;
    int j = threadIdx.x;
    float n = 0.f, d = 0.f;
    for (int i = 0; i < Hn; i++) {
        float h = g_par[l][2][i * Hn + j];
        n += h;
        d += fabsf(h);
    }
    g_cn[l][j] = n;
    g_cd[l][j] = d;
}

// ---------------- sensory precompute ----------------
__global__ void __launch_bounds__(256) sensory_kernel(int layer, const float* __restrict__ x)
{
    __shared__ float su[4][Hn];
    __shared__ float pn[4][8][Hn];
    __shared__ float pd[4][8][Hn];

    const int tg   = blockIdx.x;
    const int b    = blockIdx.y;
    const int t0   = tg * 4;
    const int tid  = threadIdx.x;
    const int w    = tid >> 5;
    const int lane = tid & 31;

    const float* ub; int ust, usb;
    if (layer == 0) { ub = x;    ust = Hn;      usb = Tn * Hn; }
    else            { ub = g_h0; ust = Bn * Hn; usb = Hn;      }

    for (int k = tid; k < 4 * Hn; k += 256) {
        int tt = k >> 7, i = k & 127;
        su[tt][i] = ub[(size_t)b * usb + (size_t)(t0 + tt) * ust + i];
    }
    __syncthreads();

    const float4* pa = (const float4*)g_par[layer][3];
    const float4* pb = (const float4*)g_par[layer][4];
    const float4* pw = (const float4*)g_par[layer][5];

    float4 an[4], ad[4];
#pragma unroll
    for (int tt = 0; tt < 4; tt++) { an[tt] = make_float4(0,0,0,0); ad[tt] = make_float4(0,0,0,0); }

#pragma unroll 2
    for (int ii = 0; ii < 16; ii++) {
        int i = w * 16 + ii;
        float4 A  = pa[i * 32 + lane];
        float4 Bv = pb[i * 32 + lane];
        float4 W  = pw[i * 32 + lane];
#pragma unroll
        for (int tt = 0; tt < 4; tt++) {
            float vi = su[tt][i];
            float th, tv;
            th = tanh_fast(fmaf(vi, A.x, Bv.x)); tv = fmaf(W.x, th, W.x); an[tt].x += tv; ad[tt].x += fabsf(tv);
            th = tanh_fast(fmaf(vi, A.y, Bv.y)); tv = fmaf(W.y, th, W.y); an[tt].y += tv; ad[tt].y += fabsf(tv);
            th = tanh_fast(fmaf(vi, A.z, Bv.z)); tv = fmaf(W.z, th, W.z); an[tt].z += tv; ad[tt].z += fabsf(tv);
            th = tanh_fast(fmaf(vi, A.w, Bv.w)); tv = fmaf(W.w, th, W.w); an[tt].w += tv; ad[tt].w += fabsf(tv);
        }
    }
#pragma unroll
    for (int tt = 0; tt < 4; tt++) {
        ((float4*)&pn[tt][w][0])[lane] = an[tt];
        ((float4*)&pd[tt][w][0])[lane] = ad[tt];
    }
    __syncthreads();

    for (int p = tid; p < 512; p += 256) {
        int tt = p >> 7, j = p & 127;
        float n = 0.f, d = 0.f;
#pragma unroll
        for (int c = 0; c < 8; c++) { n += pn[tt][c][j]; d += pd[tt][c][j]; }
        int off = ((t0 + tt) * Bn + b) * Hn + j;
        g_ns[off] = n;
        g_ds[off] = d;
    }
}

// ---------------- LTC scan: cluster-of-4, fully async mbarrier protocol ----------------
// 256 CTAs of 256 threads, 2 co-resident CTAs/SM; cluster (4,1,1) spans one batch,
// rank r owns j in [32r, 32r+32). Warp w owns 4 j's (jg = 32r+4w+lane/8), 8 lanes
// per j (s = lane&7), 16 i's per lane (i = 32q+4s+m).
// NO per-round __syncthreads: every v-update travels through the mbarrier. After
// the width-8 shfl reduce, ALL lanes compute vnew; lanes 0-3 st.async it to rank s
// (including our own rank — the local write is a tracked self-send). expect_tx =
// 128 values x 4B = 512B covers the entire next buffer, so the per-round try_wait
// is the only synchronization and warps may skew freely.
__global__ void __launch_bounds__(256, 2) __cluster_dims__(4, 1, 1)
scan_kernel(int layer, const float* __restrict__ gleak, const float* __restrict__ vleak,
            const float* __restrict__ cm)
{
    __shared__ float s_v[2][Hn];
    __shared__ __align__(16) unsigned long long s_mbar[2];

    const int tid  = threadIdx.x;
    const int w    = tid >> 5;        // 0..7
    const int lane = tid & 31;
    const int s    = lane & 7;        // i-slice within j-group
    const int jj   = lane >> 3;       // which of the warp's 4 j's
    const int b    = blockIdx.x >> 2;

    unsigned int rank;
    asm("mov.u32 %0, %%cluster_ctarank;" : "=r"(rank));

    const int jg = (int)rank * 32 + w * 4 + jj;

    const unsigned int mbar_addr = (unsigned int)__cvta_generic_to_shared(&s_mbar[0]);
    if (tid == 0) {
        asm volatile("mbarrier.init.shared.b64 [%0], 1;" :: "r"(mbar_addr)      : "memory");
        asm volatile("mbarrier.init.shared.b64 [%0], 1;" :: "r"(mbar_addr + 8u) : "memory");
    }
    if (tid < Hn) { s_v[0][tid] = 0.f; s_v[1][tid] = 0.f; }

    // ---- params into registers: k = 4q+m  ->  i = 32q + 4s + m
    float A[16], B[16], W[16];
    {
        const float* pa = g_par[layer][0];
        const float* pb = g_par[layer][1];
        const float* pw = g_par[layer][2];
#pragma unroll
        for (int q = 0; q < 4; q++)
#pragma unroll
            for (int m = 0; m < 4; m++) {
                int off = (32 * q + 4 * s + m) * Hn + jg;
                A[4*q+m] = pa[off]; B[4*q+m] = pb[off]; W[4*q+m] = pw[off];
            }
    }

    // per-j constants (all lanes of a group hold the same values)
    float g   = gleak[layer * Hn + jg];
    float vv  = vleak[layer * Hn + jg];
    float c   = cm[layer * Hn + jg];
    const float cmt  = c * (float)UNF;
    const float glr  = g;
    const float glvl = g * vv;
    const float cbn  = g_cn[layer][jg];
    const float cbd  = g_cd[layer][jg];

    // remote (and self) addresses for all 4 ranks
    unsigned int sv_all[4], mb_all[4];
    {
        unsigned int la = (unsigned int)__cvta_generic_to_shared(&s_v[0][jg]);
#pragma unroll
        for (unsigned int r = 0; r < 4; r++) {
            asm("mapa.shared::cluster.u32 %0, %1, %2;" : "=r"(sv_all[r]) : "r"(la), "r"(r));
            asm("mapa.shared::cluster.u32 %0, %1, %2;" : "=r"(mb_all[r]) : "r"(mbar_addr), "r"(r));
        }
    }

    __syncthreads();
    asm volatile("barrier.cluster.arrive.aligned;" ::: "memory");
    asm volatile("barrier.cluster.wait.aligned;"   ::: "memory");

    float* hout; int st_t, st_b;
    if (layer == 0) { hout = g_h0; st_t = Bn * Hn; st_b = Hn;      }
    else            { hout = g_h1; st_t = Hn;      st_b = Tn * Hn; }

#define STEP(vi, k) { float th = tanh_fast(fmaf((vi), A[k], B[k])); \
                      accn = fmaf(W[k], th, accn); accd = fmaf(fabsf(W[k]), th, accd); }

    float vj = 0.f;
    int cnt = 0;
    for (int t = 0; t < Tn; t++) {
        int off = (t * Bn + b) * Hn + jg;
        const float nsr = g_ns[off] + cbn;
        const float dsr = g_ds[off] + cbd;
#pragma unroll 1
        for (int u = 0; u < UNF; u++) {
            const int curb = cnt & 1;
            const int nxtb = curb ^ 1;
            if (tid == 0 && cnt < TOTAL - 1) {
                asm volatile("mbarrier.arrive.expect_tx.shared.b64 _, [%0], 512;"
                             :: "r"(mbar_addr + 8u * (unsigned)curb) : "memory");
            }
            // wait for ALL 128 values of buffer curb (sent at round cnt-1, incl. self-sends)
            if (cnt > 0) {
                const unsigned int wslot = (unsigned)((cnt - 1) & 1);
                const unsigned int wpar  = (unsigned)(((cnt - 1) >> 1) & 1);
                asm volatile(
                    "{\n\t"
                    ".reg .pred P;\n\t"
                    "WAIT_%=: \n\t"
                    "mbarrier.try_wait.parity.acquire.cta.shared::cta.b64 P, [%0], %1, 0x989680;\n\t"
                    "@P bra.uni DONE_%=;\n\t"
                    "bra.uni WAIT_%=;\n\t"
                    "DONE_%=:\n\t"
                    "}" :: "r"(mbar_addr + 8u * wslot), "r"(wpar) : "memory");
            }
            float accn = 0.f, accd = 0.f;
#pragma unroll
            for (int q = 0; q < 4; q++) {
                float4 vq = *(const float4*)&s_v[curb][32 * q + 4 * s];
                STEP(vq.x, 4*q+0) STEP(vq.y, 4*q+1) STEP(vq.z, 4*q+2) STEP(vq.w, 4*q+3)
            }
            // ---- reduce across the 8-lane group (all lanes end with full sums)
            accn += __shfl_xor_sync(0xffffffffu, accn, 1, 8);
            accd += __shfl_xor_sync(0xffffffffu, accd, 1, 8);
            accn += __shfl_xor_sync(0xffffffffu, accn, 2, 8);
            accd += __shfl_xor_sync(0xffffffffu, accd, 2, 8);
            accn += __shfl_xor_sync(0xffffffffu, accn, 4, 8);
            accd += __shfl_xor_sync(0xffffffffu, accd, 4, 8);
            // ---- redundant update on all lanes; lanes 0-3 send to rank s (incl. self)
            {
                float n = nsr + accn, d = dsr + accd;
                float vnew = __fdividef(fmaf(cmt, vj, glvl) + n, cmt + glr + d + EPSV);
                vj = vnew;
                if (cnt < TOTAL - 1 && s < 4) {
                    asm volatile("st.async.shared::cluster.mbarrier::complete_tx::bytes.b32 [%0], %1, [%2];"
                                 :: "r"(sv_all[s] + 512u * (unsigned)nxtb),
                                    "r"(__float_as_uint(vnew)),
                                    "r"(mb_all[s] + 8u * (unsigned)curb) : "memory");
                }
            }
            cnt++;
        }
        if (s == 0)
            hout[(size_t)t * st_t + (size_t)b * st_b + jg] = vj;
    }
#undef STEP
    asm volatile("barrier.cluster.arrive.aligned;" ::: "memory");
    asm volatile("barrier.cluster.wait.aligned;"   ::: "memory");
}

// ---------------- dual linear heads ----------------
__global__ void __launch_bounds__(256) head_kernel(
    const float* __restrict__ mu_w, const float* __restrict__ mu_b,
    const float* __restrict__ ls_w, const float* __restrict__ ls_b,
    float* __restrict__ out)
{
    __shared__ float  sh[64][129];
    __shared__ float4 swt[8][32];
    const int tid = threadIdx.x;
    const int bb  = tid & 63;
    const int ng  = tid >> 6;
    const int n0  = blockIdx.x * 8;
    const bool is_ls = (n0 >= LATn);
    const float* wbase = is_ls ? (ls_w + (size_t)(n0 - LATn) * (Tn * Hn))
                               : (mu_w + (size_t)n0 * (Tn * Hn));
    float acc0 = 0.f, acc1 = 0.f;

    for (int k0 = 0; k0 < Tn * Hn; k0 += 128) {
        __syncthreads();
        for (int q = tid; q < 2048; q += 256) {
            int r = q >> 5, kq = q & 31;
            float4 v = *(const float4*)(g_h1 + (size_t)r * (Tn * Hn) + k0 + kq * 4);
            sh[r][kq*4+0] = v.x; sh[r][kq*4+1] = v.y; sh[r][kq*4+2] = v.z; sh[r][kq*4+3] = v.w;
        }
        {
            int r = tid >> 5, kq = tid & 31;
            swt[r][kq] = *(const float4*)(wbase + (size_t)r * (Tn * Hn) + k0 + kq * 4);
        }
        __syncthreads();
        const int na = ng * 2, nb = ng * 2 + 1;
#pragma unroll 8
        for (int kq = 0; kq < 32; kq++) {
            float4 w0 = swt[na][kq];
            float4 w1 = swt[nb][kq];
            float h0v = sh[bb][kq*4+0], h1v = sh[bb][kq*4+1];
            float h2v = sh[bb][kq*4+2], h3v = sh[bb][kq*4+3];
            acc0 = fmaf(h0v, w0.x, fmaf(h1v, w0.y, fmaf(h2v, w0.z, fmaf(h3v, w0.w, acc0))));
            acc1 = fmaf(h0v, w1.x, fmaf(h1v, w1.y, fmaf(h2v, w1.z, fmaf(h3v, w1.w, acc1))));
        }
    }
    int na_g = n0 + ng * 2;
    float o0, o1;
    if (!is_ls) { o0 = acc0 + mu_b[na_g];              o1 = acc1 + mu_b[na_g + 1]; }
    else        { o0 = expf(acc0 + ls_b[na_g - LATn]); o1 = expf(acc1 + ls_b[na_g - LATn + 1]); }
    int outcol = is_ls ? (na_g - LATn) : na_g;
    float* ob = out + (is_ls ? (size_t)Bn * LATn : 0);
    ob[(size_t)bb * LATn + outcol]     = o0;
    ob[(size_t)bb * LATn + outcol + 1] = o1;
}

// ---------------- launch ----------------
extern "C" void kernel_launch(void* const* d_in, const int* in_sizes, int n_in,
                              void* d_out, int out_size)
{
    const float* x      = (const float*)d_in[0];
    const float* gleak  = (const float*)d_in[1];
    const float* vleak  = (const float*)d_in[2];
    const float* cm     = (const float*)d_in[3];
    const float* sigma  = (const float*)d_in[4];
    const float* mu_syn = (const float*)d_in[5];
    const float* w      = (const float*)d_in[6];
    const float* erev   = (const float*)d_in[7];
    const float* s_sig  = (const float*)d_in[8];
    const float* s_mu   = (const float*)d_in[9];
    const float* s_w    = (const float*)d_in[10];
    const float* s_er   = (const float*)d_in[11];
    const float* mu_w   = (const float*)d_in[12];
    const float* mu_b   = (const float*)d_in[13];
    const float* ls_w   = (const float*)d_in[14];
    const float* ls_b   = (const float*)d_in[15];
    float* out = (float*)d_out;

    prep_kernel<<<(Ln * Hn * Hn + 511) / 512, 512>>>(sigma, mu_syn, w, erev, s_sig, s_mu, s_w, s_er);
    csum_kernel<<<Ln, Hn>>>();

    dim3 sgrid(Tn / 4, Bn);
    sensory_kernel<<<sgrid, 256>>>(0, x);
    scan_kernel<<<4 * Bn, 256>>>(0, gleak, vleak, cm);
    sensory_kernel<<<sgrid, 256>>>(1, x);
    scan_kernel<<<4 * Bn, 256>>>(1, gleak, vleak, cm);
    head_kernel<<<(2 * LATn) / 8, 256>>>(mu_w, mu_b, ls_w, ls_b, out);
}